// round 15
// baseline (speedup 1.0000x reference)
#include <cuda_runtime.h>
#include <cuda_fp16.h>
#include <cstdint>

// ---------------------------------------------------------------- constants
#define Dm     1024
#define Bsz    8
#define Lw     4096
#define Ssent  255

#define NCHUNK 32            // k chunks of width 32
#define ROWB   80            // fp16 smem row stride bytes (32 fp16 + 16B pad)
#define TILE_A (128 * ROWB)  // fp16 A tile bytes per stage (BM = 128)

// fused prep kernel geometry
#define SG_BLKS   256        // sentence-GEMM blocks (grid prefix)
#define CVW_BLKS  8192       // words-conversion blocks
#define CVT_W_BLKS 1024      // W-conversion blocks (one per row)
#define RB4       144        // fp32 smem row stride bytes (32 f32 + 16B pad)
#define SG_TA     (128 * RB4)            // 18432
#define SG_TB     (64 * RB4)             // 9216
#define SG_STG    (SG_TA + SG_TB)        // 27648
#define SG_SMEM   (3 * SG_STG)           // 82944 (3 stages)

// ---------------------------------------------------------------- scratch
__device__ __half g_Aw[32768ull * 1024];  // words fp16
__device__ __half g_Wa[1024ull  * 1024];  // W[:, :1024] fp16
__device__ float  g_Y2[2048ull  * 1024];  // sentence pre-projection

// ---------------------------------------------------------------- PTX utils
__device__ __forceinline__ uint32_t smem_u32(const void* p) {
    uint32_t a;
    asm("{ .reg .u64 t; cvta.to.shared.u64 t, %1; cvt.u32.u64 %0, t; }"
        : "=r"(a) : "l"(p));
    return a;
}
__device__ __forceinline__ void cp16(uint32_t dst, const void* src) {
    asm volatile("cp.async.cg.shared.global [%0], [%1], 16;"
                 :: "r"(dst), "l"(src));
}
// zero-fill variant: src-size 0 -> smem gets zeros (for padded rows)
__device__ __forceinline__ void cp16z(uint32_t dst, const void* src, int valid) {
    asm volatile("cp.async.cg.shared.global [%0], [%1], 16, %2;"
                 :: "r"(dst), "l"(src), "r"(valid ? 16 : 0));
}
#define CP_COMMIT() asm volatile("cp.async.commit_group;" ::: "memory")
#define CP_WAIT(n)  asm volatile("cp.async.wait_group %0;" :: "n"(n) : "memory")

#define LDSM_X4(r, addr) \
    asm volatile("ldmatrix.sync.aligned.m8n8.x4.shared.b16 {%0,%1,%2,%3}, [%4];" \
        : "=r"((r)[0]), "=r"((r)[1]), "=r"((r)[2]), "=r"((r)[3]) : "r"(addr))

__device__ __forceinline__ void mma16816(float* c, const uint32_t* a,
                                         uint32_t b0, uint32_t b1) {
    asm volatile(
        "mma.sync.aligned.m16n8k16.row.col.f32.f16.f16.f32 "
        "{%0,%1,%2,%3}, {%4,%5,%6,%7}, {%8,%9}, {%0,%1,%2,%3};"
        : "+f"(c[0]), "+f"(c[1]), "+f"(c[2]), "+f"(c[3])
        : "r"(a[0]), "r"(a[1]), "r"(a[2]), "r"(a[3]), "r"(b0), "r"(b1));
}

__device__ __forceinline__ uint32_t packh2(float lo, float hi) {
    __half2 h = __float22half2_rn(make_float2(lo, hi));
    return *(uint32_t*)&h;
}
__device__ __forceinline__ uint32_t pack_from(const char* smem, uint32_t off) {
    float2 v = *(const float2*)(smem + off);
    return packh2(v.x, v.y);
}

// ---------------------------------------------------------------- fused prep
// blocks [0, 256): sentence GEMM  Y2[m,n] = sents[m,:] . W[n, 1024+:]  (fp32 in,
//   fp16 fragments built in-register, fp32 acc). M=2048 (pad, rows>=2040 zero),
//   N=1024, K=1024. BM=128, BN=64, 8 warps (4M x 2N), warp tile 32x32.
// blocks [256, 8448): words fp32 -> fp16 bulk conversion
// blocks [8448, 9472): W[:, :1024] -> Wa fp16 (one row per block)
__global__ __launch_bounds__(256, 2)
void prep_kernel(const float*  __restrict__ words,
                 const float*  __restrict__ sents,
                 const float*  __restrict__ W1w)
{
    const int tid = threadIdx.x;

    if (blockIdx.x >= SG_BLKS) {
        const int cb = blockIdx.x - SG_BLKS;
        if (cb < CVW_BLKS) {
            // ---- words conversion: 4 front-batched float4 per thread
            const size_t N = (size_t)CVW_BLKS * 256;
            const size_t t = (size_t)cb * 256 + tid;
            const float4* src = (const float4*)words;
            uint2* dst = (uint2*)g_Aw;
            float4 v[4];
            #pragma unroll
            for (int k = 0; k < 4; k++) v[k] = src[t + k * N];
            #pragma unroll
            for (int k = 0; k < 4; k++) {
                uint2 w;
                w.x = packh2(v[k].x, v[k].y);
                w.y = packh2(v[k].z, v[k].w);
                dst[t + k * N] = w;
            }
        } else {
            // ---- W conversion: row r, first 1024 cols -> g_Wa
            const int r = cb - CVW_BLKS;
            const int c = tid * 4;
            float4 v = *(const float4*)(W1w + (size_t)r * 2048 + c);
            uint2 w;
            w.x = packh2(v.x, v.y);
            w.y = packh2(v.z, v.w);
            *(uint2*)(g_Wa + (size_t)r * 1024 + c) = w;
        }
        return;
    }

    // ------------- sentence GEMM (fp32 operands in smem, cvt in registers)
    extern __shared__ char smem_raw[];
    char* sm = smem_raw;
    const uint32_t base = smem_u32(sm);

    const int lane = tid & 31;
    const int wid  = tid >> 5;
    const int wm   = wid >> 1;                 // 0..3 -> M offset wm*32
    const int wn   = wid & 1;                  // 0..1 -> N offset wn*32
    const int nStart = (blockIdx.x & 15) * 64; // 16 n-blocks
    const int mStart = (blockIdx.x >> 4) * 128;// 16 m-blocks (2048 pad)

    auto prefetch = [&](int u) {
        const uint32_t st = base + (u % 3) * SG_STG;
        const int k0 = u * 32;
        #pragma unroll
        for (int i = 0; i < 4; i++) {              // A: 1024 tasks (128r x 8ch)
            const int idx = tid + i * 256;
            const int row = idx >> 3, ch = idx & 7;
            const int gr = mStart + row;
            cp16z(st + row * RB4 + ch * 16,
                  sents + (size_t)gr * 1024 + k0 + ch * 4,
                  gr < Bsz * Ssent);
        }
        #pragma unroll
        for (int i = 0; i < 2; i++) {              // B: 512 tasks (64r x 8ch)
            const int idx = tid + i * 256;
            const int row = idx >> 3, ch = idx & 7;
            cp16(st + SG_TA + row * RB4 + ch * 16,
                 W1w + (size_t)(nStart + row) * 2048 + 1024 + k0 + ch * 4);
        }
        CP_COMMIT();
    };

    prefetch(0);
    prefetch(1);

    float acc[2][4][4];
    #pragma unroll
    for (int mt = 0; mt < 2; mt++)
        #pragma unroll
        for (int j = 0; j < 4; j++)
            #pragma unroll
            for (int v = 0; v < 4; v++) acc[mt][j][v] = 0.f;

    const int fr = lane >> 2;          // fragment row/col group
    const int fc = (lane & 3) * 2;

    for (int t = 0; t < NCHUNK; t++) {
        if (t < NCHUNK - 1) CP_WAIT(1); else CP_WAIT(0);
        __syncthreads();
        if (t + 2 < NCHUNK) prefetch(t + 2);

        const char* st = sm + (t % 3) * SG_STG;
        const char* sB = st + SG_TA;

        #pragma unroll
        for (int kk = 0; kk < 2; kk++) {
            const int c0 = kk * 16 + fc;           // k columns (fp32 words)
            // B fragments: n8 tile j, rows n = wn*32 + j*8 + fr
            uint32_t b0[4], b1[4];
            #pragma unroll
            for (int j = 0; j < 4; j++) {
                const uint32_t bo = (uint32_t)(wn * 32 + j * 8 + fr) * RB4;
                b0[j] = pack_from(sB, bo + c0 * 4);
                b1[j] = pack_from(sB, bo + (c0 + 8) * 4);
            }
            #pragma unroll
            for (int mt = 0; mt < 2; mt++) {
                const uint32_t r0 = (uint32_t)(wm * 32 + mt * 16 + fr) * RB4;
                const uint32_t r1 = r0 + 8 * RB4;
                uint32_t a[4];
                a[0] = pack_from(st, r0 + c0 * 4);
                a[1] = pack_from(st, r1 + c0 * 4);
                a[2] = pack_from(st, r0 + (c0 + 8) * 4);
                a[3] = pack_from(st, r1 + (c0 + 8) * 4);
                #pragma unroll
                for (int j = 0; j < 4; j++)
                    mma16816(acc[mt][j], a, b0[j], b1[j]);
            }
        }
    }

    // epilogue: raw float2 stores into g_Y2 (pitch 1024)
    const int rBase = mStart + wm * 32 + fr;
    const int cBase = nStart + wn * 32 + fc;
    #pragma unroll
    for (int mt = 0; mt < 2; mt++)
        #pragma unroll
        for (int rs = 0; rs < 2; rs++) {
            const int row = rBase + mt * 16 + rs * 8;
            float* op = g_Y2 + (size_t)row * 1024;
            #pragma unroll
            for (int j = 0; j < 4; j++)
                *(float2*)(op + cBase + j * 8) =
                    make_float2(acc[mt][j][rs * 2 + 0], acc[mt][j][rs * 2 + 1]);
        }
}

// ---------------------------------------------------------------- main GEMM
// out[m,n] = relu( words_f16[m,:].Wa[n,:] + bias[n] + gather(Y2) )
// BM=128, BN=128, K=1024, 4-stage cp.async pipeline, fp16 HMMA, fp32 acc.
#define STAGES 4
#define STG    (TILE_A + 128 * ROWB)      // 20480
#define SM_MAIN (STAGES * STG)            // 81920

__global__ __launch_bounds__(256, 2)
void main_gemm(const __half* __restrict__ Ap,    // pitch 1024
               const __half* __restrict__ Bp,    // pitch 1024
               const float*  __restrict__ bias,
               const int*    __restrict__ smap,
               const float*  __restrict__ y2,
               float* __restrict__ out)
{
    extern __shared__ char smem_raw[];
    const uint32_t base = smem_u32(smem_raw);

    const int tid  = threadIdx.x;
    const int lane = tid & 31;
    const int wid  = tid >> 5;
    const int wm   = wid >> 1;
    const int wn   = wid & 1;
    const int nStart = blockIdx.x * 128;   // N fastest: A block shared via L2
    const int mStart = blockIdx.y * 128;

    auto prefetch = [&](int u) {
        const uint32_t st = base + (u % STAGES) * STG;
        const int k0 = u * 32;
        #pragma unroll
        for (int i = 0; i < 2; i++) {
            const int idx = tid + i * 256;
            const int row = idx >> 2, ch = idx & 3;
            cp16(st + row * ROWB + ch * 16,
                 Ap + (size_t)(mStart + row) * 1024 + k0 + ch * 8);
        }
        #pragma unroll
        for (int i = 0; i < 2; i++) {
            const int idx = tid + i * 256;
            const int row = idx >> 2, ch = idx & 3;
            cp16(st + TILE_A + row * ROWB + ch * 16,
                 Bp + (size_t)(nStart + row) * 1024 + k0 + ch * 8);
        }
        CP_COMMIT();
    };

    #pragma unroll
    for (int s = 0; s < STAGES - 1; s++) prefetch(s);

    float acc[2][8][4];
    #pragma unroll
    for (int mt = 0; mt < 2; mt++)
        #pragma unroll
        for (int nt = 0; nt < 8; nt++)
            #pragma unroll
            for (int j = 0; j < 4; j++) acc[mt][nt][j] = 0.f;

    const uint32_t aOff = (uint32_t)(wm * 32 + (lane & 15)) * ROWB
                        + ((lane >> 4) * 16);
    const uint32_t bOff = (uint32_t)(wn * 64 + ((lane >> 4) & 1) * 8 + (lane & 7)) * ROWB
                        + (((lane >> 3) & 1) * 16);

    for (int t = 0; t < NCHUNK; t++) {
        const int allow = NCHUNK - 1 - t;        // groups allowed outstanding
        if (allow >= STAGES - 2) { CP_WAIT(STAGES - 2); }
        else if (allow == 1)     { CP_WAIT(1); }
        else                     { CP_WAIT(0); }
        __syncthreads();

        if (t + STAGES - 1 < NCHUNK) prefetch(t + STAGES - 1);

        const uint32_t st = base + (t % STAGES) * STG;
        const uint32_t aS = st + aOff;
        const uint32_t bS = st + TILE_A + bOff;

        #pragma unroll
        for (int kk = 0; kk < 2; kk++) {
            const uint32_t kb = kk * 32;
            uint32_t b[4][4];
            #pragma unroll
            for (int q = 0; q < 4; q++)
                LDSM_X4(b[q], bS + q * 16 * ROWB + kb);

            uint32_t a[2][4];
            LDSM_X4(a[0], aS + kb);
            LDSM_X4(a[1], aS + 16 * ROWB + kb);

            #pragma unroll
            for (int mt = 0; mt < 2; mt++)
                #pragma unroll
                for (int q = 0; q < 4; q++) {
                    mma16816(acc[mt][2 * q + 0], a[mt], b[q][0], b[q][1]);
                    mma16816(acc[mt][2 * q + 1], a[mt], b[q][2], b[q][3]);
                }
        }
    }

    // epilogue: bias + gathered sentence projection + ReLU
    const int rBase = mStart + wm * 32 + (lane >> 2);
    const int cBase = nStart + wn * 64 + (lane & 3) * 2;

    float2 bias2[8];
    #pragma unroll
    for (int nt = 0; nt < 8; nt++)
        bias2[nt] = *(const float2*)(bias + cBase + nt * 8);

    #pragma unroll
    for (int mt = 0; mt < 2; mt++)
        #pragma unroll
        for (int rs = 0; rs < 2; rs++) {
            const int row = rBase + mt * 16 + rs * 8;
            const int sv = smap[row];
            const int bb = row >> 12;                  // Lw = 4096
            const float* yrow = g_Y2
                + (size_t)(bb * Ssent + (sv < 0 ? 0 : sv)) * 1024;
            float* op = out + (size_t)row * 1024;
            #pragma unroll
            for (int nt = 0; nt < 8; nt++) {
                const int col = cBase + nt * 8;
                float2 yv = make_float2(0.f, 0.f);
                if (sv >= 0) yv = *(const float2*)(yrow + col);
                float2 o;
                o.x = fmaxf(acc[mt][nt][rs * 2 + 0] + bias2[nt].x + yv.x, 0.f);
                o.y = fmaxf(acc[mt][nt][rs * 2 + 1] + bias2[nt].y + yv.y, 0.f);
                *(float2*)(op + col) = o;
            }
        }
}

// ---------------------------------------------------------------- launch
extern "C" void kernel_launch(void* const* d_in, const int* in_sizes, int n_in,
                              void* d_out, int out_size)
{
    const float* words = (const float*)d_in[0];  // [8, 4096, 1024]
    const float* sents = (const float*)d_in[1];  // [8, 255, 1024]
    const float* W1w   = (const float*)d_in[2];  // [1024, 2048]
    const float* W1b   = (const float*)d_in[3];  // [1024]
    const int*   smap  = (const int*)d_in[4];    // [8, 4096]
    float*       out   = (float*)d_out;          // [8, 4096, 1024]

    void *pAw, *pWa;
    cudaGetSymbolAddress(&pAw, g_Aw);
    cudaGetSymbolAddress(&pWa, g_Wa);

    cudaFuncSetAttribute((const void*)prep_kernel,
                         cudaFuncAttributeMaxDynamicSharedMemorySize, SG_SMEM);
    cudaFuncSetAttribute((const void*)main_gemm,
                         cudaFuncAttributeMaxDynamicSharedMemorySize, SM_MAIN);

    // Launch 1: sentence GEMM (from fp32) + words/W conversions, one grid.
    prep_kernel<<<SG_BLKS + CVW_BLKS + CVT_W_BLKS, 256, SG_SMEM>>>(
        words, sents, W1w);

    // Launch 2: main GEMM with fused gather + bias + ReLU.
    dim3 gridM(Dm / 128, (Bsz * Lw) / 128);      // 8 x 256
    main_gemm<<<gridM, 256, SM_MAIN>>>(
        (const __half*)pAw, (const __half*)pWa,
        W1b, smap, g_Y2, out);
}